// round 13
// baseline (speedup 1.0000x reference)
#include <cuda_runtime.h>
#include <cstdint>

#define CASCADES 3
#define GS3 16777216              // 256^3 cells per cascade
#define NCOORD 4194304            // GS3 / 4 coords per cascade
#define TOTAL_CELLS (CASCADES * GS3)          // 50331648
#define BITS_BYTES  (TOTAL_CELLS / 8)         // 6291456

// Scratch: per-cell winner = (coord_index + 1), 0 = no write.
// Statically zero-initialized; combine_k restores zeros after reading, so
// every call (and every graph replay) sees a clean array. No zero kernel.
__device__ unsigned g_win[TOTAL_CELLS];

__device__ __forceinline__ unsigned p1b2(unsigned x) {
    x &= 0x3FFu;
    x = (x | (x << 16)) & 0x030000FFu;
    x = (x | (x << 8))  & 0x0300F00Fu;
    x = (x | (x << 4))  & 0x030C30C3u;
    x = (x | (x << 2))  & 0x09249249u;
    return x;
}
__device__ __forceinline__ unsigned morton(unsigned x, unsigned y, unsigned z) {
    return p1b2(x) | (p1b2(y) << 1) | (p1b2(z) << 2);
}

// 4 coords per thread: 3 x int4 streaming loads, 4 fire-and-forget RED.MAX.
// (R1 form, known-fast.)
__global__ void scatter_k(const int4* __restrict__ coords4,
                          unsigned* __restrict__ win) {
    int t = blockIdx.x * blockDim.x + threadIdx.x;   // t < NCOORD/4
    if (t >= NCOORD / 4) return;
    int4 a = __ldcs(coords4 + 3 * t + 0);
    int4 b = __ldcs(coords4 + 3 * t + 1);
    int4 c = __ldcs(coords4 + 3 * t + 2);
    unsigned base = 4u * (unsigned)t;
    unsigned m0 = morton((unsigned)a.x, (unsigned)a.y, (unsigned)a.z);
    unsigned m1 = morton((unsigned)a.w, (unsigned)b.x, (unsigned)b.y);
    unsigned m2 = morton((unsigned)b.z, (unsigned)b.w, (unsigned)c.x);
    unsigned m3 = morton((unsigned)c.y, (unsigned)c.z, (unsigned)c.w);
    // last-write-wins: highest coord index wins (matches sequential scatter)
    atomicMax(win + m0, base + 1u);
    atomicMax(win + m1, base + 2u);
    atomicMax(win + m2, base + 3u);
    atomicMax(win + m3, base + 4u);
}

// R1-form combine (8 cells/thread, plain loads/stores, inline gather) with
// EXACTLY ONE change: after reading win, store zeros back (plain stores,
// L2-hit on the just-read lines) so the separate zero pass is eliminated.
template <int FLOATBITS>
__global__ void combine_k(const float* __restrict__ density,
                          const float* __restrict__ sigmas,
                          unsigned* __restrict__ win,
                          float* __restrict__ out_grid,
                          uint8_t* __restrict__ out_bits_u8,
                          float* __restrict__ out_bits_f) {
    int t = blockIdx.x * blockDim.x + threadIdx.x;   // one byte (8 cells)
    if (t >= GS3 / 8) return;

    uint4* wp = (uint4*)win + 2 * t;
    uint4 w0 = wp[0];
    uint4 w1 = wp[1];
    wp[0] = make_uint4(0u, 0u, 0u, 0u);   // reset for next call's scatter
    wp[1] = make_uint4(0u, 0u, 0u, 0u);

    float4 d0 = ((const float4*)density)[2 * t + 0];
    float4 d1 = ((const float4*)density)[2 * t + 1];

    unsigned ws[8] = {w0.x, w0.y, w0.z, w0.w, w1.x, w1.y, w1.z, w1.w};
    float    dv[8] = {d0.x, d0.y, d0.z, d0.w, d1.x, d1.y, d1.z, d1.w};
    float    v[8];
    unsigned byte = 0u;

#pragma unroll
    for (int b = 0; b < 8; b++) {
        float val = dv[b];
        unsigned w = ws[b];
        if (w) {
            float s = __ldg(sigmas + (w - 1u));   // DENSITY_SCALE == 1.0
            if (val >= 0.0f && s >= 0.0f)         // valid = old>=0 && new>=0
                val = fmaxf(0.95f * val, s);      // DECAY = 0.95
        }
        v[b] = val;
        if (val > 0.01f) byte |= (1u << b);       // DENSITY_THRESHOLD = 0.01
    }

    ((float4*)out_grid)[2 * t + 0] = make_float4(v[0], v[1], v[2], v[3]);
    ((float4*)out_grid)[2 * t + 1] = make_float4(v[4], v[5], v[6], v[7]);

    if (FLOATBITS) {
        out_bits_f[t] = (float)byte;
    } else {
        out_bits_u8[t] = (uint8_t)byte;
    }
}

extern "C" void kernel_launch(void* const* d_in, const int* in_sizes, int n_in,
                              void* d_out, int out_size) {
    const float* density = (const float*)d_in[0];   // [3, 256^3] f32
    const float* sigmas  = (const float*)d_in[1];   // [3, NCOORD] f32
    const int*   coords  = (const int*)d_in[2];     // [3, NCOORD, 3] i32

    unsigned* win = nullptr;
    cudaGetSymbolAddress((void**)&win, g_win);

    // Output layout: reference returns (new_grid f32, bitfield u8).
    const long long f32_elems = (long long)TOTAL_CELLS + (long long)BITS_BYTES;
    bool floatbits = ((long long)out_size == f32_elems);

    float*   out_grid = (float*)d_out;
    uint8_t* bits_u8  = (uint8_t*)d_out + (size_t)TOTAL_CELLS * 4;
    float*   bits_f   = (float*)d_out + (size_t)TOTAL_CELLS;

    const int SB = (NCOORD / 4) / 256;   // scatter blocks (4 coords/thread)
    const int CB = (GS3 / 8) / 256;      // combine blocks (8 cells/thread)

    // Per-cascade serial pipeline (best-known structure), 6 launches total:
    // scatter -> combine per cascade; combine re-zeros win for the next call.
    for (int c = 0; c < CASCADES; c++) {
        unsigned*    winc = win + (size_t)c * GS3;
        const float* denc = density + (size_t)c * GS3;
        const float* sigc = sigmas + (size_t)c * NCOORD;
        const int4*  crdc = (const int4*)(coords + (size_t)c * NCOORD * 3);

        scatter_k<<<SB, 256>>>(crdc, winc);
        if (floatbits) {
            combine_k<1><<<CB, 256>>>(denc, sigc, winc,
                                      out_grid + (size_t)c * GS3,
                                      nullptr,
                                      bits_f + (size_t)c * (GS3 / 8));
        } else {
            combine_k<0><<<CB, 256>>>(denc, sigc, winc,
                                      out_grid + (size_t)c * GS3,
                                      bits_u8 + (size_t)c * (GS3 / 8),
                                      nullptr);
        }
    }
}

// round 14
// speedup vs baseline: 1.6246x; 1.6246x over previous
#include <cuda_runtime.h>
#include <cstdint>

#define CASCADES 3
#define GS3 16777216              // 256^3 cells per cascade
#define NCOORD 4194304            // GS3 / 4 coords per cascade
#define TOTAL_CELLS (CASCADES * GS3)          // 50331648
#define BITS_BYTES  (TOTAL_CELLS / 8)         // 6291456

// Scratch: per-cell winner = (coord_index + 1), 0 = no write.
// Zeroed by a dedicated zero_k each cascade (measured: L2-absorbed, DRAM ~8%;
// fusing the reset into combine costs +140us total — R13).
__device__ unsigned g_win[TOTAL_CELLS];

__device__ __forceinline__ unsigned p1b2(unsigned x) {
    x &= 0x3FFu;
    x = (x | (x << 16)) & 0x030000FFu;
    x = (x | (x << 8))  & 0x0300F00Fu;
    x = (x | (x << 4))  & 0x030C30C3u;
    x = (x | (x << 2))  & 0x09249249u;
    return x;
}
__device__ __forceinline__ unsigned morton(unsigned x, unsigned y, unsigned z) {
    return p1b2(x) | (p1b2(y) << 1) | (p1b2(z) << 2);
}

__global__ void zero_k(uint4* __restrict__ p, int n4) {
    int i = blockIdx.x * blockDim.x + threadIdx.x;
    if (i < n4) p[i] = make_uint4(0u, 0u, 0u, 0u);
}

// 4 coords per thread: 3 x int4 streaming loads, 4 fire-and-forget RED.MAX.
// (R1 form, known-fast.)
__global__ void scatter_k(const int4* __restrict__ coords4,
                          unsigned* __restrict__ win) {
    int t = blockIdx.x * blockDim.x + threadIdx.x;   // t < NCOORD/4
    if (t >= NCOORD / 4) return;
    int4 a = __ldcs(coords4 + 3 * t + 0);
    int4 b = __ldcs(coords4 + 3 * t + 1);
    int4 c = __ldcs(coords4 + 3 * t + 2);
    unsigned base = 4u * (unsigned)t;
    unsigned m0 = morton((unsigned)a.x, (unsigned)a.y, (unsigned)a.z);
    unsigned m1 = morton((unsigned)a.w, (unsigned)b.x, (unsigned)b.y);
    unsigned m2 = morton((unsigned)b.z, (unsigned)b.w, (unsigned)c.x);
    unsigned m3 = morton((unsigned)c.y, (unsigned)c.z, (unsigned)c.w);
    // last-write-wins: highest coord index wins (matches sequential scatter)
    atomicMax(win + m0, base + 1u);
    atomicMax(win + m1, base + 2u);
    atomicMax(win + m2, base + 3u);
    atomicMax(win + m3, base + 4u);
}

// R1-form combine (8 cells/thread, plain loads/stores, read-only win) with
// ONE change: all 8 sigma gathers are issued back-to-back BEFORE the compute
// loop (8 independent predicated L2 transactions in flight per thread).
template <int FLOATBITS>
__global__ void combine_k(const float* __restrict__ density,
                          const float* __restrict__ sigmas,
                          const unsigned* __restrict__ win,
                          float* __restrict__ out_grid,
                          uint8_t* __restrict__ out_bits_u8,
                          float* __restrict__ out_bits_f) {
    int t = blockIdx.x * blockDim.x + threadIdx.x;   // one byte (8 cells)
    if (t >= GS3 / 8) return;

    uint4 w0 = ((const uint4*)win)[2 * t + 0];
    uint4 w1 = ((const uint4*)win)[2 * t + 1];
    float4 d0 = ((const float4*)density)[2 * t + 0];
    float4 d1 = ((const float4*)density)[2 * t + 1];

    unsigned ws[8] = {w0.x, w0.y, w0.z, w0.w, w1.x, w1.y, w1.z, w1.w};
    float    dv[8] = {d0.x, d0.y, d0.z, d0.w, d1.x, d1.y, d1.z, d1.w};

    // Hoisted gathers: 8 independent predicated loads, maximum gather MLP.
    float sg[8];
#pragma unroll
    for (int b = 0; b < 8; b++)
        sg[b] = ws[b] ? __ldg(sigmas + (ws[b] - 1u)) : -1.0f;

    float    v[8];
    unsigned byte = 0u;
#pragma unroll
    for (int b = 0; b < 8; b++) {
        float val = dv[b];
        if (ws[b]) {
            float s = sg[b];                      // DENSITY_SCALE == 1.0
            if (val >= 0.0f && s >= 0.0f)         // valid = old>=0 && new>=0
                val = fmaxf(0.95f * val, s);      // DECAY = 0.95
        }
        v[b] = val;
        if (val > 0.01f) byte |= (1u << b);       // DENSITY_THRESHOLD = 0.01
    }

    ((float4*)out_grid)[2 * t + 0] = make_float4(v[0], v[1], v[2], v[3]);
    ((float4*)out_grid)[2 * t + 1] = make_float4(v[4], v[5], v[6], v[7]);

    if (FLOATBITS) {
        out_bits_f[t] = (float)byte;
    } else {
        out_bits_u8[t] = (uint8_t)byte;
    }
}

extern "C" void kernel_launch(void* const* d_in, const int* in_sizes, int n_in,
                              void* d_out, int out_size) {
    const float* density = (const float*)d_in[0];   // [3, 256^3] f32
    const float* sigmas  = (const float*)d_in[1];   // [3, NCOORD] f32
    const int*   coords  = (const int*)d_in[2];     // [3, NCOORD, 3] i32

    unsigned* win = nullptr;
    cudaGetSymbolAddress((void**)&win, g_win);

    // Output layout: reference returns (new_grid f32, bitfield u8).
    const long long f32_elems = (long long)TOTAL_CELLS + (long long)BITS_BYTES;
    bool floatbits = ((long long)out_size == f32_elems);

    float*   out_grid = (float*)d_out;
    uint8_t* bits_u8  = (uint8_t*)d_out + (size_t)TOTAL_CELLS * 4;
    float*   bits_f   = (float*)d_out + (size_t)TOTAL_CELLS;

    const int ZB = (GS3 / 4) / 256;      // zero blocks (uint4 granularity)
    const int SB = (NCOORD / 4) / 256;   // scatter blocks (4 coords/thread)
    const int CB = (GS3 / 8) / 256;      // combine blocks (8 cells/thread)

    // Per-cascade serial pipeline: zero -> scatter -> combine on one stream.
    // This exact structure measured fastest (R1: 256.6us); all deviations
    // (stream overlap, shared win buffer, merged phases, fused reset) lost.
    for (int c = 0; c < CASCADES; c++) {
        unsigned*    winc = win + (size_t)c * GS3;
        const float* denc = density + (size_t)c * GS3;
        const float* sigc = sigmas + (size_t)c * NCOORD;
        const int4*  crdc = (const int4*)(coords + (size_t)c * NCOORD * 3);

        zero_k<<<ZB, 256>>>((uint4*)winc, GS3 / 4);
        scatter_k<<<SB, 256>>>(crdc, winc);
        if (floatbits) {
            combine_k<1><<<CB, 256>>>(denc, sigc, winc,
                                      out_grid + (size_t)c * GS3,
                                      nullptr,
                                      bits_f + (size_t)c * (GS3 / 8));
        } else {
            combine_k<0><<<CB, 256>>>(denc, sigc, winc,
                                      out_grid + (size_t)c * GS3,
                                      bits_u8 + (size_t)c * (GS3 / 8),
                                      nullptr);
        }
    }
}